// round 5
// baseline (speedup 1.0000x reference)
#include <cuda_runtime.h>

#define NQ   6
#define DIM  64
#define TT   512
#define BB   128

// Fixed per-direction unitaries: U[dir][row][col], built by setup_kernel.
__device__ float2 U_g[2][DIM][DIM];

__device__ __forceinline__ float2 cmul(float2 a, float2 b) {
    return make_float2(a.x * b.x - a.y * b.y, a.x * b.y + a.y * b.x);
}
__device__ __forceinline__ float2 cadd(float2 a, float2 b) {
    return make_float2(a.x + b.x, a.y + b.y);
}

// ---------------------------------------------------------------------------
// Setup: build U = V(params) * Q(poly) as a 64x64 complex matrix per direction.
// One CTA per direction, 64 threads, matrix in shared memory.
// Gates act on rows (state index i); wire w <-> bit (5-w) of i.
// ---------------------------------------------------------------------------
__global__ void setup_kernel(const float* __restrict__ poly,
                             const float* __restrict__ fwd_params,
                             const float* __restrict__ bwd_params)
{
    __shared__ float2 M[DIM][DIM];
    const int dir = blockIdx.x;
    const float* params = dir ? bwd_params : fwd_params;
    const int tid = threadIdx.x;  // 0..63

    // identity
    for (int j = 0; j < DIM; ++j)
        M[tid][j] = make_float2(tid == j ? 1.f : 0.f, 0.f);
    __syncthreads();

    // ---- QSVT block: 4 x (diagonal phase, then CNOT ring) ----
    for (int d = 0; d <= 3; ++d) {
        float theta = poly[d] * 3.14159265358979323846f;
        float sign  = (float)NQ - 2.0f * (float)__popc(tid);
        float ang   = -0.5f * theta * sign;
        float2 ph;
        sincosf(ang, &ph.y, &ph.x);               // ph = exp(i*ang)
        for (int j = 0; j < DIM; ++j)             // row tid scaled by phase[tid]
            M[tid][j] = cmul(ph, M[tid][j]);
        __syncthreads();
        for (int cw = 0; cw < NQ; ++cw) {         // CNOT(0,1)..(4,5),(5,0)
            int c  = (cw < NQ - 1) ? cw : NQ - 1;
            int t  = (cw < NQ - 1) ? cw + 1 : 0;
            int mc = 1 << (NQ - 1 - c), mt = 1 << (NQ - 1 - t);
            for (int i = 0; i < DIM; ++i) {       // thread = column
                if ((i & mc) && !(i & mt)) {
                    float2 a = M[i][tid];
                    M[i][tid]      = M[i | mt][tid];
                    M[i | mt][tid] = a;
                }
            }
            __syncthreads();
        }
    }

    // ---- Variational: 2 layers of (RZ*RY*RX per wire, then CNOT chain) ----
    int idx = 0;
    for (int layer = 0; layer < 2; ++layer) {
        for (int w = 0; w < NQ; ++w) {
            float al = params[idx], be = params[idx + 1], ga = params[idx + 2];
            idx += 3;
            float ca, sa, cb, sb, cg, sg;
            sincosf(0.5f * al, &sa, &ca);
            sincosf(0.5f * be, &sb, &cb);
            sincosf(0.5f * ga, &sg, &cg);
            // RX = [[ca, -i sa], [-i sa, ca]]
            float2 X00 = make_float2(ca, 0.f),  X01 = make_float2(0.f, -sa);
            float2 X10 = make_float2(0.f, -sa), X11 = make_float2(ca, 0.f);
            // RY = [[cb, -sb], [sb, cb]]
            float2 Y00 = make_float2(cb, 0.f),  Y01 = make_float2(-sb, 0.f);
            float2 Y10 = make_float2(sb, 0.f),  Y11 = make_float2(cb, 0.f);
            // A = RY * RX
            float2 A00 = cadd(cmul(Y00, X00), cmul(Y01, X10));
            float2 A01 = cadd(cmul(Y00, X01), cmul(Y01, X11));
            float2 A10 = cadd(cmul(Y10, X00), cmul(Y11, X10));
            float2 A11 = cadd(cmul(Y10, X01), cmul(Y11, X11));
            // U1 = RZ * A,  RZ = diag(e^{-i g/2}, e^{+i g/2})
            float2 Z0 = make_float2(cg, -sg), Z1 = make_float2(cg, sg);
            float2 u00 = cmul(Z0, A00), u01 = cmul(Z0, A01);
            float2 u10 = cmul(Z1, A10), u11 = cmul(Z1, A11);
            int m = 1 << (NQ - 1 - w);
            for (int i0 = 0; i0 < DIM; ++i0) {    // thread = column
                if (i0 & m) continue;
                float2 a = M[i0][tid], b = M[i0 | m][tid];
                M[i0][tid]     = cadd(cmul(u00, a), cmul(u01, b));
                M[i0 | m][tid] = cadd(cmul(u10, a), cmul(u11, b));
            }
            __syncthreads();
        }
        for (int c = 0; c < NQ - 1; ++c) {        // CNOT chain (no ring)
            int t  = c + 1;
            int mc = 1 << (NQ - 1 - c), mt = 1 << (NQ - 1 - t);
            for (int i = 0; i < DIM; ++i) {
                if ((i & mc) && !(i & mt)) {
                    float2 a = M[i][tid];
                    M[i][tid]      = M[i | mt][tid];
                    M[i | mt][tid] = a;
                }
            }
            __syncthreads();
        }
    }

    for (int j = 0; j < DIM; ++j)
        U_g[dir][tid][j] = M[tid][j];
}

// ---------------------------------------------------------------------------
// Main scan: 1 CTA per (direction, batch) lane; 64 threads = 1 amplitude each.
// ---------------------------------------------------------------------------
__global__ void __launch_bounds__(64)
hydra_kernel(const float* __restrict__ angles,
             const float* __restrict__ fwd_coeff,
             const float* __restrict__ bwd_coeff,
             float* __restrict__ out)
{
    const int cta = blockIdx.x;
    const int dir = cta >> 7;
    const int b   = cta & 127;
    const int tid = threadIdx.x;

    // U row in registers (constant across the whole scan)
    float2 Urow[DIM];
#pragma unroll
    for (int j = 0; j < DIM; ++j)
        Urow[j] = U_g[dir][tid][j];

    __shared__ float hs[8];
    __shared__ float chs[8], shs[8], cxs[8], sxs[8];
    __shared__ float p0[DIM];
    __shared__ float exch[2 * DIM];
    __shared__ float pex[DIM];

    float cf    = dir ? bwd_coeff[0] : fwd_coeff[0];
    float coeff = 1.0f / (1.0f + expf(-cf));

    if (tid < NQ) hs[tid] = 0.f;

    // prefetch angles for step 0
    float ax = 0.f;
    {
        int t0 = dir ? (TT - 1) : 0;
        if (tid >= 8 && tid < 8 + NQ)
            ax = angles[((size_t)b * TT + t0) * NQ + (tid - 8)];
    }
    __syncthreads();

    const unsigned FULL = 0xFFFFFFFFu;

    for (int step = 0; step < TT; ++step) {
        const int t = dir ? (TT - 1 - step) : step;

        // sincos of h (threads 0..5) and x (threads 8..13)
        if (tid < NQ) {
            float s, c; sincosf(0.5f * hs[tid], &s, &c);
            chs[tid] = c; shs[tid] = s;
        } else if (tid >= 8 && tid < 8 + NQ) {
            float s, c; sincosf(0.5f * ax, &s, &c);
            cxs[tid - 8] = c; sxs[tid - 8] = s;
        }
        __syncthreads();

        // prefetch next step's angles (latency hidden under this step)
        if (tid >= 8 && tid < 8 + NQ && step + 1 < TT) {
            int tn = dir ? (TT - 2 - step) : (step + 1);
            ax = angles[((size_t)b * TT + tn) * NQ + (tid - 8)];
        }

        // psi0[tid] = prod_w (bit ? sin : cos)   (real product state)
        float v = 1.f;
#pragma unroll
        for (int w = 0; w < NQ; ++w)
            v *= ((tid >> (NQ - 1 - w)) & 1) ? shs[w] : chs[w];
        p0[tid] = v;
        __syncthreads();

        // psi1[tid] = sum_j U[tid][j] * p0[j]   (complex row . real vec)
        float re0 = 0.f, re1 = 0.f, im0 = 0.f, im1 = 0.f;
#pragma unroll
        for (int j = 0; j < DIM; j += 2) {
            float pa = p0[j], pb = p0[j + 1];
            re0 = fmaf(Urow[j].x, pa, re0);
            im0 = fmaf(Urow[j].y, pa, im0);
            re1 = fmaf(Urow[j + 1].x, pb, re1);
            im1 = fmaf(Urow[j + 1].y, pb, im1);
        }
        float re = re0 + re1, im = im0 + im1;

        // RY(x) on wire 0 (bit 5, cross-warp) via shared exchange
        exch[tid] = re; exch[DIM + tid] = im;
        __syncthreads();
        {
            float pre = exch[tid ^ 32];
            float pim = exch[DIM + (tid ^ 32)];
            float c = cxs[0], s = sxs[0];
            float sg = (tid & 32) ? s : -s;        // new = c*self + (bit? +s:-s)*partner
            re = fmaf(sg, pre, c * re);
            im = fmaf(sg, pim, c * im);
        }
        // RY(x) wires 1..5 (bits 4..0, within-warp) via shfl
#pragma unroll
        for (int w = 1; w < NQ; ++w) {
            int m = 1 << (NQ - 1 - w);
            float c = cxs[w], s = sxs[w];
            float pre = __shfl_xor_sync(FULL, re, m);
            float pim = __shfl_xor_sync(FULL, im, m);
            float sg = (tid & m) ? s : -s;
            re = fmaf(sg, pre, c * re);
            im = fmaf(sg, pim, c * im);
        }

        // Walsh-Hadamard transform of probabilities: thread k ends with
        // sum_j p_j * (-1)^{popc(j & k)}; index k = 1<<(5-w) is <Z_w>.
        float p = re * re + im * im;
#pragma unroll
        for (int m = 1; m <= 16; m <<= 1) {
            float pp = __shfl_xor_sync(FULL, p, m);
            p = (tid & m) ? (pp - p) : (pp + p);
        }
        pex[tid] = p;
        __syncthreads();
        {
            float pp = pex[tid ^ 32];
            p = (tid & 32) ? (pp - p) : (pp + p);
        }

        // threads at single-bit indices hold z_w; update h and emit output
        if (tid == 32 || tid == 16 || tid == 8 || tid == 4 || tid == 2 || tid == 1) {
            int w = (NQ - 1) - (31 - __clz(tid));
            hs[w] = p;
            atomicAdd(&out[((size_t)b * TT + t) * NQ + w], coeff * p);
        }
        __syncthreads();
    }
}

__global__ void zero_kernel(float* __restrict__ out, int n)
{
    int i = blockIdx.x * blockDim.x + threadIdx.x;
    if (i < n) out[i] = 0.f;
}

extern "C" void kernel_launch(void* const* d_in, const int* in_sizes, int n_in,
                              void* d_out, int out_size)
{
    const float* angles = (const float*)d_in[0];
    const float* poly   = (const float*)d_in[1];
    const float* fwdp   = (const float*)d_in[2];
    const float* bwdp   = (const float*)d_in[3];
    const float* fwdc   = (const float*)d_in[4];
    const float* bwdc   = (const float*)d_in[5];
    float* out = (float*)d_out;

    zero_kernel<<<(out_size + 255) / 256, 256>>>(out, out_size);
    setup_kernel<<<2, 64>>>(poly, fwdp, bwdp);
    hydra_kernel<<<2 * BB, 64>>>(angles, fwdc, bwdc, out);
}